// round 5
// baseline (speedup 1.0000x reference)
#include <cuda_runtime.h>
#include <cuda_bf16.h>
#include <math.h>
#include <stdint.h>

#define D    128
#define Bn   4
#define NSn  10000
#define NTn  10000
#define En   160000
#define Kc   16
#define LDS_T 136
#define LDC   132
#define NT128 5000          // (Bn*En)/128 tiles for persistent bond kernel

// ---------------- scratch ----------------
__device__ float g_Ps  [Bn * NSn * D];
__device__ float g_Pt  [Bn * NTn * D];
__device__ float g_Ptt [Bn * NTn * D];
__device__ float g_db  [Bn * En  * D];
__device__ float g_red [Bn * NTn * D];
__device__ __nv_bfloat16 g_Wh[5 * D * D];   // 0=W_s2e 1=W_t2e 2=W_e2e 3=W_e2t 4=W_t2t
__device__ __nv_bfloat16 g_Wl[5 * D * D];

// ---------------- PTX helpers ----------------
__device__ __forceinline__ uint32_t smem_u32(const void* p) {
    return (uint32_t)__cvta_generic_to_shared(p);
}
__device__ __forceinline__ void ldsm4(uint32_t a, uint32_t& r0, uint32_t& r1, uint32_t& r2, uint32_t& r3) {
    asm volatile("ldmatrix.sync.aligned.m8n8.x4.shared.b16 {%0,%1,%2,%3}, [%4];"
                 : "=r"(r0), "=r"(r1), "=r"(r2), "=r"(r3) : "r"(a));
}
__device__ __forceinline__ void ldsm4t(uint32_t a, uint32_t& r0, uint32_t& r1, uint32_t& r2, uint32_t& r3) {
    asm volatile("ldmatrix.sync.aligned.m8n8.x4.trans.shared.b16 {%0,%1,%2,%3}, [%4];"
                 : "=r"(r0), "=r"(r1), "=r"(r2), "=r"(r3) : "r"(a));
}
__device__ __forceinline__ void mma16816(float c[4], uint32_t a0, uint32_t a1, uint32_t a2, uint32_t a3,
                                         uint32_t b0, uint32_t b1) {
    asm volatile("mma.sync.aligned.m16n8k16.row.col.f32.bf16.bf16.f32 "
                 "{%0,%1,%2,%3},{%4,%5,%6,%7},{%8,%9},{%0,%1,%2,%3};"
                 : "+f"(c[0]), "+f"(c[1]), "+f"(c[2]), "+f"(c[3])
                 : "r"(a0), "r"(a1), "r"(a2), "r"(a3), "r"(b0), "r"(b1));
}
__device__ __forceinline__ void split2(float2 v, uint32_t& hi, uint32_t& lo) {
    __nv_bfloat16 hx = __float2bfloat16(v.x), hy = __float2bfloat16(v.y);
    __nv_bfloat162 h; h.x = hx; h.y = hy;
    __nv_bfloat162 l;
    l.x = __float2bfloat16(v.x - __bfloat162float(hx));
    l.y = __float2bfloat16(v.y - __bfloat162float(hy));
    hi = *(uint32_t*)&h;
    lo = *(uint32_t*)&l;
}
__device__ __forceinline__ float silu_f(float x) { return x / (1.0f + __expf(-x)); }

// ---------------- weight pre-split ----------------
__global__ __launch_bounds__(256) void prep_w_kernel(const float* __restrict__ W0,
                                                     const float* __restrict__ W1,
                                                     const float* __restrict__ W2,
                                                     const float* __restrict__ W3,
                                                     const float* __restrict__ W4) {
    int i = blockIdx.x * 256 + threadIdx.x;
    int w = i >> 14, j = i & (D * D - 1);
    const float* W = (w == 0) ? W0 : (w == 1) ? W1 : (w == 2) ? W2 : (w == 3) ? W3 : W4;
    float x = W[j];
    __nv_bfloat16 h = __float2bfloat16(x);
    g_Wh[i] = h;
    g_Wl[i] = __float2bfloat16(x - __bfloat162float(h));
}

// ---------------- shared HMMA pieces (R2-proven) ----------------
__device__ __forceinline__ void load_W_tile(__nv_bfloat16* Wh, __nv_bfloat16* Wl, int widx,
                                            int tid, int nthr) {
    const __nv_bfloat16* gh = g_Wh + widx * D * D;
    const __nv_bfloat16* gl = g_Wl + widx * D * D;
    for (int i = tid; i < D * 16; i += nthr) {
        int r = i >> 4, c = (i & 15) * 8;
        *(uint4*)(Wh + r * LDS_T + c) = *(const uint4*)(gh + r * D + c);
        *(uint4*)(Wl + r * LDS_T + c) = *(const uint4*)(gl + r * D + c);
    }
}
__device__ __forceinline__ void load_X_split(__nv_bfloat16* Xh, __nv_bfloat16* Xl,
                                             const float* __restrict__ Xg, int tid) {
    #pragma unroll
    for (int i = tid; i < 64 * 32; i += 256) {
        int r = i >> 5, c = (i & 31) * 4;
        float4 v = *(const float4*)(Xg + (size_t)r * D + c);
        uint32_t h0, l0, h1, l1;
        split2(make_float2(v.x, v.y), h0, l0);
        split2(make_float2(v.z, v.w), h1, l1);
        *(uint32_t*)(Xh + r * LDS_T + c)     = h0;
        *(uint32_t*)(Xh + r * LDS_T + c + 2) = h1;
        *(uint32_t*)(Xl + r * LDS_T + c)     = l0;
        *(uint32_t*)(Xl + r * LDS_T + c + 2) = l1;
    }
}
__device__ __forceinline__ void gemm_mma64(const __nv_bfloat16* Xh, const __nv_bfloat16* Xl,
                                           const __nv_bfloat16* Wh, const __nv_bfloat16* Wl,
                                           int tid, float acc[8][4]) {
    int lane = tid & 31, w = tid >> 5;
    int rg = (w & 3) * 16, cg = (w >> 2) * 64;
    #pragma unroll
    for (int i = 0; i < 8; i++)
        #pragma unroll
        for (int j = 0; j < 4; j++) acc[i][j] = 0.0f;
    int l7 = lane & 7, lm = lane >> 3;
    int a_row = rg + l7 + ((lm & 1) << 3);
    int a_cad = (lm >> 1) << 3;
    uint32_t aH = smem_u32(Xh + a_row * LDS_T + a_cad);
    uint32_t aL = smem_u32(Xl + a_row * LDS_T + a_cad);
    int b_krow = l7 + ((lm & 1) << 3);
    int b_cad  = (lm >> 1) << 3;
    uint32_t bH[4], bL[4];
    #pragma unroll
    for (int nr = 0; nr < 4; nr++) {
        int col = cg + nr * 16 + b_cad;
        bH[nr] = smem_u32(Wh + b_krow * LDS_T + col);
        bL[nr] = smem_u32(Wl + b_krow * LDS_T + col);
    }
    #pragma unroll
    for (int k0 = 0; k0 < D; k0 += 16) {
        uint32_t ah0, ah1, ah2, ah3, al0, al1, al2, al3;
        ldsm4(aH + k0 * 2, ah0, ah1, ah2, ah3);
        ldsm4(aL + k0 * 2, al0, al1, al2, al3);
        uint32_t koff = (uint32_t)(k0 * LDS_T * 2);
        #pragma unroll
        for (int nr = 0; nr < 4; nr++) {
            uint32_t bh0, bh1, bh2, bh3, bl0, bl1, bl2, bl3;
            ldsm4t(bH[nr] + koff, bh0, bh1, bh2, bh3);
            ldsm4t(bL[nr] + koff, bl0, bl1, bl2, bl3);
            mma16816(acc[2 * nr],     ah0, ah1, ah2, ah3, bh0, bh1);
            mma16816(acc[2 * nr],     ah0, ah1, ah2, ah3, bl0, bl1);
            mma16816(acc[2 * nr],     al0, al1, al2, al3, bh0, bh1);
            mma16816(acc[2 * nr + 1], ah0, ah1, ah2, ah3, bh2, bh3);
            mma16816(acc[2 * nr + 1], ah0, ah1, ah2, ah3, bl2, bl3);
            mma16816(acc[2 * nr + 1], al0, al1, al2, al3, bh2, bh3);
        }
    }
}
__device__ __forceinline__ void stage_acc(float* Cs, const float acc[8][4], int tid) {
    int lane = tid & 31, w = tid >> 5;
    int rg = (w & 3) * 16, cg = (w >> 2) * 64;
    int gid = lane >> 2, tid4 = lane & 3;
    #pragma unroll
    for (int nt = 0; nt < 8; nt++) {
        int col = cg + nt * 8 + tid4 * 2;
        int row = rg + gid;
        *(float2*)(Cs + row * LDC + col)       = make_float2(acc[nt][0], acc[nt][1]);
        *(float2*)(Cs + (row + 8) * LDC + col) = make_float2(acc[nt][2], acc[nt][3]);
    }
}
__device__ __forceinline__ void silu_ln(float v[4], const float gg[4], const float bb[4],
                                        float out[4]) {
    #pragma unroll
    for (int c = 0; c < 4; c++) v[c] = silu_f(v[c]);
    float s1 = v[0] + v[1] + v[2] + v[3];
    float s2 = v[0]*v[0] + v[1]*v[1] + v[2]*v[2] + v[3]*v[3];
    #pragma unroll
    for (int o = 16; o > 0; o >>= 1) {
        s1 += __shfl_xor_sync(0xFFFFFFFFu, s1, o);
        s2 += __shfl_xor_sync(0xFFFFFFFFu, s2, o);
    }
    float m   = s1 * (1.0f / D);
    float var = fmaxf(s2 * (1.0f / D) - m * m, 0.0f);
    float rs  = rsqrtf(var + 1e-5f);
    #pragma unroll
    for (int c = 0; c < 4; c++) out[c] = (v[c] - m) * rs * gg[c] + bb[c];
}

#define SM_SINGLE ((2 * 64 * LDS_T + 2 * D * LDS_T) * 2)
#define SM_DUAL   ((2 * 64 * LDS_T + 4 * D * LDS_T) * 2)

// ---------------- kernel 1: src @ W_s2e -> g_Ps ----------------
__global__ __launch_bounds__(256) void proj_src_kernel(const float* __restrict__ src) {
    extern __shared__ char sm[];
    __nv_bfloat16* Xh = (__nv_bfloat16*)sm;
    __nv_bfloat16* Xl = Xh + 64 * LDS_T;
    __nv_bfloat16* Wh = Xl + 64 * LDS_T;
    __nv_bfloat16* Wl = Wh + D * LDS_T;
    float* Cs = (float*)sm;
    int tid = threadIdx.x;
    int row0 = blockIdx.x * 64;
    load_W_tile(Wh, Wl, 0, tid, 256);
    load_X_split(Xh, Xl, src + (size_t)row0 * D, tid);
    __syncthreads();
    float acc[8][4];
    gemm_mma64(Xh, Xl, Wh, Wl, tid, acc);
    __syncthreads();
    stage_acc(Cs, acc, tid);
    __syncthreads();
    int tx = tid & 31, ty = tid >> 5;
    #pragma unroll
    for (int r = 0; r < 8; r++) {
        float4 v = *(float4*)(Cs + (ty * 8 + r) * LDC + tx * 4);
        *(float4*)(g_Ps + (size_t)(row0 + ty * 8 + r) * D + tx * 4) = v;
    }
}

// ---------------- kernel 2: tgt dual proj ----------------
__global__ __launch_bounds__(256) void proj_tgt_dual_kernel(const float* __restrict__ tgt) {
    extern __shared__ char sm[];
    __nv_bfloat16* Xh  = (__nv_bfloat16*)sm;
    __nv_bfloat16* Xl  = Xh + 64 * LDS_T;
    __nv_bfloat16* Wh1 = Xl + 64 * LDS_T;
    __nv_bfloat16* Wl1 = Wh1 + D * LDS_T;
    __nv_bfloat16* Wh2 = Wl1 + D * LDS_T;
    __nv_bfloat16* Wl2 = Wh2 + D * LDS_T;
    float* Cs = (float*)Wh1;
    int tid = threadIdx.x;
    int row0 = blockIdx.x * 64;
    load_W_tile(Wh1, Wl1, 1, tid, 256);
    load_W_tile(Wh2, Wl2, 4, tid, 256);
    load_X_split(Xh, Xl, tgt + (size_t)row0 * D, tid);
    __syncthreads();
    int tx = tid & 31, ty = tid >> 5;
    {
        float acc[8][4];
        gemm_mma64(Xh, Xl, Wh1, Wl1, tid, acc);
        __syncthreads();
        stage_acc(Cs, acc, tid);
        __syncthreads();
        #pragma unroll
        for (int r = 0; r < 8; r++) {
            float4 v = *(float4*)(Cs + (ty * 8 + r) * LDC + tx * 4);
            *(float4*)(g_Pt + (size_t)(row0 + ty * 8 + r) * D + tx * 4) = v;
        }
        __syncthreads();
    }
    {
        float acc[8][4];
        gemm_mma64(Xh, Xl, Wh2, Wl2, tid, acc);
        __syncthreads();
        stage_acc(Cs, acc, tid);
        __syncthreads();
        #pragma unroll
        for (int r = 0; r < 8; r++) {
            float4 v = *(float4*)(Cs + (ty * 8 + r) * LDC + tx * 4);
            *(float4*)(g_Ptt + (size_t)(row0 + ty * 8 + r) * D + tx * 4) = v;
        }
    }
}

// ================= persistent HMMA bond kernel =================
// smem (bytes): X double buffer (hi+lo each 128x136 bf16): 2*69632
//               W hi/lo: 69632; LN partials 4KB; gamma/beta 1KB
#define BXH(b)  ((b) * 69632)
#define BXL(b)  ((b) * 69632 + 34816)
#define BWH     139264
#define BWL     174080
#define BPART   208896
#define BSG     212992
#define BSB     213504
#define SM_BONDP 214016

__global__ __launch_bounds__(512, 1) void bond_kernel(const float* __restrict__ bond,
        const float* __restrict__ g1, const float* __restrict__ b1,
        const int* __restrict__ src_order, const int* __restrict__ tgt_order,
        float* __restrict__ out0) {
    extern __shared__ char sm[];
    uint32_t smb = smem_u32(sm);
    int tid = threadIdx.x, lane = tid & 31, wrp = tid >> 5;   // 16 warps
    int rg = wrp & 3, cg = wrp >> 2;                          // 4x4 warp grid
    int G = gridDim.x, bid = blockIdx.x;

    // persistent W (W_e2e) + LN params
    load_W_tile((__nv_bfloat16*)(sm + BWH), (__nv_bfloat16*)(sm + BWL), 2, tid, 512);
    if (tid < D) {
        ((float*)(sm + BSG))[tid] = g1[tid];
        ((float*)(sm + BSB))[tid] = b1[tid];
    }

    int n = (NT128 - bid + G - 1) / G;
    if (n <= 0) { __syncthreads(); return; }

    // prefetch thread mapping: 4 threads per row, 32 fp32 cols each
    int prow = tid >> 2;
    int pcol = (tid & 3) * 32;

    // preload tile 0 into buffer 0
    {
        const float* sp = bond + ((size_t)bid * 128 + prow) * D + pcol;
        char* xh = sm + BXH(0);
        char* xl = sm + BXL(0);
        #pragma unroll
        for (int j = 0; j < 8; j++) {
            float4 v = *(const float4*)(sp + j * 4);
            uint32_t h0, l0, h1, l1;
            split2(make_float2(v.x, v.y), h0, l0);
            split2(make_float2(v.z, v.w), h1, l1);
            int c = pcol + j * 4;
            *(uint2*)(xh + (prow * LDS_T + c) * 2) = make_uint2(h0, h1);
            *(uint2*)(xl + (prow * LDS_T + c) * 2) = make_uint2(l0, l1);
        }
    }
    __syncthreads();

    // fragment offsets (bytes)
    int l7 = lane & 7, lm = lane >> 3;
    int acad = (lm >> 1) << 3;
    uint32_t aoff[2], boff[2];
    #pragma unroll
    for (int mt = 0; mt < 2; mt++)
        aoff[mt] = (uint32_t)(((rg * 32 + mt * 16 + l7 + ((lm & 1) << 3)) * LDS_T + acad) * 2);
    #pragma unroll
    for (int nt = 0; nt < 2; nt++)
        boff[nt] = (uint32_t)(((l7 + ((lm & 1) << 3)) * LDS_T + cg * 32 + nt * 16 + acad) * 2);
    uint32_t whb = smb + BWH, wlb = smb + BWL;

    int g = lane >> 2, t4 = lane & 3;
    int colb = cg * 32 + t4 * 2;

    for (int i = 0; i < n; i++) {
        int cb = i & 1;
        uint32_t xhb = smb + BXH(cb), xlb = smb + BXL(cb);
        bool pf = (i + 1 < n);
        const float* np = pf ? (bond + (((size_t)(bid + (size_t)(i + 1) * G)) * 128 + prow) * D + pcol)
                             : bond;
        char* nxh = sm + BXH(cb ^ 1);
        char* nxl = sm + BXL(cb ^ 1);

        float acc[2][4][4];
        #pragma unroll
        for (int a = 0; a < 2; a++)
            #pragma unroll
            for (int bq = 0; bq < 4; bq++)
                #pragma unroll
                for (int j = 0; j < 4; j++) acc[a][bq][j] = 0.0f;

        float4 pbuf[4];
        if (pf) {
            #pragma unroll
            for (int j = 0; j < 4; j++) pbuf[j] = *(const float4*)(np + j * 4);
        }

        // ---- MMA k = 0..63 ----
        #pragma unroll
        for (int kk = 0; kk < 4; kk++) {
            int k0 = kk * 16;
            uint32_t ah[2][4], al[2][4];
            ldsm4(xhb + aoff[0] + k0 * 2, ah[0][0], ah[0][1], ah[0][2], ah[0][3]);
            ldsm4(xlb + aoff[0] + k0 * 2, al[0][0], al[0][1], al[0][2], al[0][3]);
            ldsm4(xhb + aoff[1] + k0 * 2, ah[1][0], ah[1][1], ah[1][2], ah[1][3]);
            ldsm4(xlb + aoff[1] + k0 * 2, al[1][0], al[1][1], al[1][2], al[1][3]);
            uint32_t ko = (uint32_t)(k0 * LDS_T * 2);
            #pragma unroll
            for (int nt = 0; nt < 2; nt++) {
                uint32_t bh0, bh1, bh2, bh3, bl0, bl1, bl2, bl3;
                ldsm4t(whb + boff[nt] + ko, bh0, bh1, bh2, bh3);
                ldsm4t(wlb + boff[nt] + ko, bl0, bl1, bl2, bl3);
                #pragma unroll
                for (int mt = 0; mt < 2; mt++) {
                    mma16816(acc[mt][2 * nt],     ah[mt][0], ah[mt][1], ah[mt][2], ah[mt][3], bh0, bh1);
                    mma16816(acc[mt][2 * nt],     ah[mt][0], ah[mt][1], ah[mt][2], ah[mt][3], bl0, bl1);
                    mma16816(acc[mt][2 * nt],     al[mt][0], al[mt][1], al[mt][2], al[mt][3], bh0, bh1);
                    mma16816(acc[mt][2 * nt + 1], ah[mt][0], ah[mt][1], ah[mt][2], ah[mt][3], bh2, bh3);
                    mma16816(acc[mt][2 * nt + 1], ah[mt][0], ah[mt][1], ah[mt][2], ah[mt][3], bl2, bl3);
                    mma16816(acc[mt][2 * nt + 1], al[mt][0], al[mt][1], al[mt][2], al[mt][3], bh2, bh3);
                }
            }
        }

        // ---- store prefetch batch A, issue batch B ----
        float4 pbuf2[4];
        if (pf) {
            #pragma unroll
            for (int j = 0; j < 4; j++) {
                uint32_t h0, l0, h1, l1;
                split2(make_float2(pbuf[j].x, pbuf[j].y), h0, l0);
                split2(make_float2(pbuf[j].z, pbuf[j].w), h1, l1);
                int c = pcol + j * 4;
                *(uint2*)(nxh + (prow * LDS_T + c) * 2) = make_uint2(h0, h1);
                *(uint2*)(nxl + (prow * LDS_T + c) * 2) = make_uint2(l0, l1);
            }
            #pragma unroll
            for (int j = 0; j < 4; j++) pbuf2[j] = *(const float4*)(np + 16 + j * 4);
        }

        // ---- MMA k = 64..127 ----
        #pragma unroll
        for (int kk = 4; kk < 8; kk++) {
            int k0 = kk * 16;
            uint32_t ah[2][4], al[2][4];
            ldsm4(xhb + aoff[0] + k0 * 2, ah[0][0], ah[0][1], ah[0][2], ah[0][3]);
            ldsm4(xlb + aoff[0] + k0 * 2, al[0][0], al[0][1], al[0][2], al[0][3]);
            ldsm4(xhb + aoff[1] + k0 * 2, ah[1][0], ah[1][1], ah[1][2], ah[1][3]);
            ldsm4(xlb + aoff[1] + k0 * 2, al[1][0], al[1][1], al[1][2], al[1][3]);
            uint32_t ko = (uint32_t)(k0 * LDS_T * 2);
            #pragma unroll
            for (int nt = 0; nt < 2; nt++) {
                uint32_t bh0, bh1, bh2, bh3, bl0, bl1, bl2, bl3;
                ldsm4t(whb + boff[nt] + ko, bh0, bh1, bh2, bh3);
                ldsm4t(wlb + boff[nt] + ko, bl0, bl1, bl2, bl3);
                #pragma unroll
                for (int mt = 0; mt < 2; mt++) {
                    mma16816(acc[mt][2 * nt],     ah[mt][0], ah[mt][1], ah[mt][2], ah[mt][3], bh0, bh1);
                    mma16816(acc[mt][2 * nt],     ah[mt][0], ah[mt][1], ah[mt][2], ah[mt][3], bl0, bl1);
                    mma16816(acc[mt][2 * nt],     al[mt][0], al[mt][1], al[mt][2], al[mt][3], bh0, bh1);
                    mma16816(acc[mt][2 * nt + 1], ah[mt][0], ah[mt][1], ah[mt][2], ah[mt][3], bh2, bh3);
                    mma16816(acc[mt][2 * nt + 1], ah[mt][0], ah[mt][1], ah[mt][2], ah[mt][3], bl2, bl3);
                    mma16816(acc[mt][2 * nt + 1], al[mt][0], al[mt][1], al[mt][2], al[mt][3], bh2, bh3);
                }
            }
        }

        // ---- store prefetch batch B ----
        if (pf) {
            #pragma unroll
            for (int j = 0; j < 4; j++) {
                uint32_t h0, l0, h1, l1;
                split2(make_float2(pbuf2[j].x, pbuf2[j].y), h0, l0);
                split2(make_float2(pbuf2[j].z, pbuf2[j].w), h1, l1);
                int c = pcol + 16 + j * 4;
                *(uint2*)(nxh + (prow * LDS_T + c) * 2) = make_uint2(h0, h1);
                *(uint2*)(nxl + (prow * LDS_T + c) * 2) = make_uint2(l0, l1);
            }
        }

        // ---- epilogue: silu + cross-warp LN + gather + store ----
        size_t row0 = (size_t)(bid + (size_t)i * G) * 128;
        int bb_ = (int)(row0 / En);
        int ebase = (int)(row0 - (size_t)bb_ * En);
        const float* PsB = g_Ps + (size_t)bb_ * NSn * D;
        const float* PtB = g_Pt + (size_t)bb_ * NTn * D;

        #pragma unroll
        for (int m2 = 0; m2 < 4; m2++) {
            int r = rg * 32 + (m2 >> 1) * 16 + (m2 & 1) * 8 + g;
            int so = src_order[ebase + r];
            int to = tgt_order[ebase + r];
            const float* ps = PsB + (size_t)so * D;
            const float* pt = PtB + (size_t)to * D;
            float s1 = 0.f, s2 = 0.f;
            int jj = (m2 & 1) * 2;
            #pragma unroll
            for (int nt = 0; nt < 2; nt++)
                #pragma unroll
                for (int h = 0; h < 2; h++) {
                    int c = colb + nt * 16 + h * 8;
                    float2 p = *(const float2*)(ps + c);
                    float2 q = *(const float2*)(pt + c);
                    float* a = acc[m2 >> 1][2 * nt + h];
                    float v0 = silu_f(a[jj]     + p.x + q.x);
                    float v1 = silu_f(a[jj + 1] + p.y + q.y);
                    a[jj] = v0; a[jj + 1] = v1;
                    s1 += v0 + v1;
                    s2 += v0 * v0 + v1 * v1;
                }
            s1 += __shfl_xor_sync(0xFFFFFFFFu, s1, 1);
            s2 += __shfl_xor_sync(0xFFFFFFFFu, s2, 1);
            s1 += __shfl_xor_sync(0xFFFFFFFFu, s1, 2);
            s2 += __shfl_xor_sync(0xFFFFFFFFu, s2, 2);
            if (t4 == 0)
                *(float2*)(sm + BPART + (r * 4 + cg) * 8) = make_float2(s1, s2);
        }
        __syncthreads();

        #pragma unroll
        for (int m2 = 0; m2 < 4; m2++) {
            int r = rg * 32 + (m2 >> 1) * 16 + (m2 & 1) * 8 + g;
            float2 p0 = *(float2*)(sm + BPART + (r * 4 + 0) * 8);
            float2 p1 = *(float2*)(sm + BPART + (r * 4 + 1) * 8);
            float2 p2 = *(float2*)(sm + BPART + (r * 4 + 2) * 8);
            float2 p3 = *(float2*)(sm + BPART + (r * 4 + 3) * 8);
            float S1 = p0.x + p1.x + p2.x + p3.x;
            float S2 = p0.y + p1.y + p2.y + p3.y;
            float mM = S1 * (1.0f / D);
            float rs = rsqrtf(fmaxf(S2 * (1.0f / D) - mM * mM, 0.0f) + 1e-5f);
            float* db = g_db + (row0 + r) * D;
            float* oo = out0 + (row0 + r) * D;
            const char* xrh = sm + BXH(cb) + r * LDS_T * 2;
            const char* xrl = sm + BXL(cb) + r * LDS_T * 2;
            int jj = (m2 & 1) * 2;
            #pragma unroll
            for (int nt = 0; nt < 2; nt++)
                #pragma unroll
                for (int h = 0; h < 2; h++) {
                    int c = colb + nt * 16 + h * 8;
                    float2 gg = *(const float2*)((const float*)(sm + BSG) + c);
                    float2 be = *(const float2*)((const float*)(sm + BSB) + c);
                    __nv_bfloat162 H = *(const __nv_bfloat162*)(xrh + c * 2);
                    __nv_bfloat162 L = *(const __nv_bfloat162*)(xrl + c * 2);
                    float x0 = __bfloat162float(H.x) + __bfloat162float(L.x);
                    float x1 = __bfloat162float(H.y) + __bfloat162float(L.y);
                    const float* a = acc[m2 >> 1][2 * nt + h];
                    float d0 = (a[jj]     - mM) * rs * gg.x + be.x;
                    float d1 = (a[jj + 1] - mM) * rs * gg.y + be.y;
                    *(float2*)(db + c) = make_float2(d0, d1);
                    *(float2*)(oo + c) = make_float2(x0 + d0, x1 + d1);
                }
        }
        __syncthreads();
    }
}

// ---------------- kernel 4: bond_reduce ----------------
__global__ __launch_bounds__(256) void reduce_kernel(const int* __restrict__ edge_order,
                                                     const float* __restrict__ coef) {
    int tid  = threadIdx.x;
    int lane = tid & 31;
    int node = (blockIdx.x * blockDim.x + tid) >> 5;
    int b = node / NTn;
    int t = node - b * NTn;
    int   e_l = 0;
    float c_l = 0.0f;
    if (lane < Kc) {
        e_l = edge_order[t * Kc + lane];
        c_l = coef[t * Kc + lane];
    }
    float4 acc = {0.f, 0.f, 0.f, 0.f};
    #pragma unroll
    for (int k = 0; k < Kc; k++) {
        int   e = __shfl_sync(0xFFFFFFFFu, e_l, k);
        float c = __shfl_sync(0xFFFFFFFFu, c_l, k);
        float4 v = *(const float4*)(g_db + ((size_t)b * En + e) * D + lane * 4);
        acc.x += c * v.x;
        acc.y += c * v.y;
        acc.z += c * v.z;
        acc.w += c * v.w;
    }
    const float inv = 1.0f / Kc;
    acc.x *= inv; acc.y *= inv; acc.z *= inv; acc.w *= inv;
    *(float4*)(g_red + (size_t)node * D + lane * 4) = acc;
}

// ---------------- kernel 5: d_tgt ----------------
__global__ __launch_bounds__(256) void tgt_kernel(const float* __restrict__ tgt,
                                                  const float* __restrict__ g2,
                                                  const float* __restrict__ b2,
                                                  float* __restrict__ out2) {
    extern __shared__ char sm[];
    __nv_bfloat16* Xh = (__nv_bfloat16*)sm;
    __nv_bfloat16* Xl = Xh + 64 * LDS_T;
    __nv_bfloat16* Wh = Xl + 64 * LDS_T;
    __nv_bfloat16* Wl = Wh + D * LDS_T;
    float* Cs = (float*)sm;
    int tid = threadIdx.x;
    int row0 = blockIdx.x * 64;
    load_W_tile(Wh, Wl, 3, tid, 256);
    load_X_split(Xh, Xl, g_red + (size_t)row0 * D, tid);
    __syncthreads();
    float acc[8][4];
    gemm_mma64(Xh, Xl, Wh, Wl, tid, acc);
    __syncthreads();
    stage_acc(Cs, acc, tid);
    __syncthreads();

    int tx = tid & 31, ty = tid >> 5;
    float gg[4], bb[4];
    #pragma unroll
    for (int c = 0; c < 4; c++) { gg[c] = g2[tx * 4 + c]; bb[c] = b2[tx * 4 + c]; }
    #pragma unroll
    for (int r = 0; r < 8; r++) {
        int row = row0 + ty * 8 + r;
        float4 cv = *(float4*)(Cs + (ty * 8 + r) * LDC + tx * 4);
        float4 pt = *(const float4*)(g_Ptt + (size_t)row * D + tx * 4);
        float v[4];
        v[0] = cv.x + pt.x;
        v[1] = cv.y + pt.y;
        v[2] = cv.z + pt.z;
        v[3] = cv.w + pt.w;
        float d[4];
        silu_ln(v, gg, bb, d);
        float4 tin = *(const float4*)(tgt + (size_t)row * D + tx * 4);
        float4 o2 = {tin.x + d[0], tin.y + d[1], tin.z + d[2], tin.w + d[3]};
        *(float4*)(out2 + (size_t)row * D + tx * 4) = o2;
    }
}

// ---------------- launch ----------------
extern "C" void kernel_launch(void* const* d_in, const int* in_sizes, int n_in,
                              void* d_out, int out_size) {
    const float* bond  = (const float*)d_in[0];
    const float* src   = (const float*)d_in[1];
    const float* tgt   = (const float*)d_in[2];
    const float* W_s2e = (const float*)d_in[3];
    const float* W_t2e = (const float*)d_in[4];
    const float* W_e2e = (const float*)d_in[5];
    const float* ln1_g = (const float*)d_in[6];
    const float* ln1_b = (const float*)d_in[7];
    const float* W_e2t = (const float*)d_in[8];
    const float* W_t2t = (const float*)d_in[9];
    const float* ln2_g = (const float*)d_in[10];
    const float* ln2_b = (const float*)d_in[11];
    const float* coef  = (const float*)d_in[12];
    const int*   so    = (const int*)d_in[13];
    const int*   to    = (const int*)d_in[14];
    const int*   eo    = (const int*)d_in[15];

    float* out  = (float*)d_out;
    float* out0 = out;
    float* out1 = out0 + (size_t)Bn * En * D;
    float* out2 = out1 + (size_t)Bn * NSn * D;

    int nsm = 148;
    cudaDeviceGetAttribute(&nsm, cudaDevAttrMultiProcessorCount, 0);

    cudaFuncSetAttribute(proj_src_kernel,      cudaFuncAttributeMaxDynamicSharedMemorySize, SM_SINGLE);
    cudaFuncSetAttribute(proj_tgt_dual_kernel, cudaFuncAttributeMaxDynamicSharedMemorySize, SM_DUAL);
    cudaFuncSetAttribute(bond_kernel,          cudaFuncAttributeMaxDynamicSharedMemorySize, SM_BONDP);
    cudaFuncSetAttribute(tgt_kernel,           cudaFuncAttributeMaxDynamicSharedMemorySize, SM_SINGLE);

    prep_w_kernel<<<320, 256>>>(W_s2e, W_t2e, W_e2e, W_e2t, W_t2t);

    proj_src_kernel<<<(Bn * NSn) / 64, 256, SM_SINGLE>>>(src);
    proj_tgt_dual_kernel<<<(Bn * NTn) / 64, 256, SM_DUAL>>>(tgt);

    cudaMemcpyAsync(out1, src, (size_t)Bn * NSn * D * sizeof(float),
                    cudaMemcpyDeviceToDevice, 0);

    bond_kernel<<<nsm, 512, SM_BONDP>>>(bond, ln1_g, ln1_b, so, to, out0);

    reduce_kernel<<<(Bn * NTn) / 8, 256>>>(eo, coef);

    tgt_kernel<<<(Bn * NTn) / 64, 256, SM_SINGLE>>>(tgt, ln2_g, ln2_b, out2);
}

// round 6
// speedup vs baseline: 1.2092x; 1.2092x over previous
#include <cuda_runtime.h>
#include <cuda_bf16.h>
#include <math.h>
#include <stdint.h>

#define D    128
#define Bn   4
#define NSn  10000
#define NTn  10000
#define En   160000
#define Kc   16
#define LDS_T 136   // padded bf16 row (272B, 16B-aligned, ldmatrix conflict-free)
#define LDC   132   // padded fp32 C row

// ---------------- scratch ----------------
__device__ float g_Ps  [Bn * NSn * D];
__device__ float g_Pt  [Bn * NTn * D];
__device__ float g_Ptt [Bn * NTn * D];
__device__ float g_db  [Bn * En  * D];
__device__ float g_red [Bn * NTn * D];
__device__ __nv_bfloat16 g_Wh[5 * D * D];   // 0=W_s2e 1=W_t2e 2=W_e2e 3=W_e2t 4=W_t2t
__device__ __nv_bfloat16 g_Wl[5 * D * D];

// ---------------- PTX helpers ----------------
__device__ __forceinline__ uint32_t smem_u32(const void* p) {
    return (uint32_t)__cvta_generic_to_shared(p);
}
__device__ __forceinline__ void ldsm4(uint32_t a, uint32_t r[4]) {
    asm volatile("ldmatrix.sync.aligned.m8n8.x4.shared.b16 {%0,%1,%2,%3}, [%4];"
                 : "=r"(r[0]), "=r"(r[1]), "=r"(r[2]), "=r"(r[3]) : "r"(a));
}
__device__ __forceinline__ void ldsm4t(uint32_t a, uint32_t r[4]) {
    asm volatile("ldmatrix.sync.aligned.m8n8.x4.trans.shared.b16 {%0,%1,%2,%3}, [%4];"
                 : "=r"(r[0]), "=r"(r[1]), "=r"(r[2]), "=r"(r[3]) : "r"(a));
}
__device__ __forceinline__ void mma16816(float c[4], const uint32_t a[4],
                                         uint32_t b0, uint32_t b1) {
    asm volatile("mma.sync.aligned.m16n8k16.row.col.f32.bf16.bf16.f32 "
                 "{%0,%1,%2,%3},{%4,%5,%6,%7},{%8,%9},{%0,%1,%2,%3};"
                 : "+f"(c[0]), "+f"(c[1]), "+f"(c[2]), "+f"(c[3])
                 : "r"(a[0]), "r"(a[1]), "r"(a[2]), "r"(a[3]), "r"(b0), "r"(b1));
}
__device__ __forceinline__ void cp16(uint32_t dst, const void* src) {
    asm volatile("cp.async.cg.shared.global [%0], [%1], 16;" :: "r"(dst), "l"(src));
}
__device__ __forceinline__ void cp_commit() { asm volatile("cp.async.commit_group;"); }
__device__ __forceinline__ void cp_wait0()  { asm volatile("cp.async.wait_group 0;"); }
__device__ __forceinline__ void pref_l2(const void* p) {
    asm volatile("prefetch.global.L2 [%0];" :: "l"(p));
}
__device__ __forceinline__ void split2(float2 v, uint32_t& hi, uint32_t& lo) {
    __nv_bfloat16 hx = __float2bfloat16(v.x), hy = __float2bfloat16(v.y);
    __nv_bfloat162 h; h.x = hx; h.y = hy;
    __nv_bfloat162 l;
    l.x = __float2bfloat16(v.x - __bfloat162float(hx));
    l.y = __float2bfloat16(v.y - __bfloat162float(hy));
    hi = *(uint32_t*)&h;
    lo = *(uint32_t*)&l;
}
__device__ __forceinline__ float silu_f(float x) { return x / (1.0f + __expf(-x)); }

// ---------------- weight pre-split ----------------
__global__ __launch_bounds__(256) void prep_w_kernel(const float* __restrict__ W0,
                                                     const float* __restrict__ W1,
                                                     const float* __restrict__ W2,
                                                     const float* __restrict__ W3,
                                                     const float* __restrict__ W4) {
    int i = blockIdx.x * 256 + threadIdx.x;
    int w = i >> 14, j = i & (D * D - 1);
    const float* W = (w == 0) ? W0 : (w == 1) ? W1 : (w == 2) ? W2 : (w == 3) ? W3 : W4;
    float x = W[j];
    __nv_bfloat16 h = __float2bfloat16(x);
    g_Wh[i] = h;
    g_Wl[i] = __float2bfloat16(x - __bfloat162float(h));
}

// ---------------- tile loads ----------------
// cp.async W load: issue only (caller commits/waits)
__device__ __forceinline__ void load_W_cp(__nv_bfloat16* Wh, __nv_bfloat16* Wl, int widx, int tid) {
    const __nv_bfloat16* gh = g_Wh + widx * D * D;
    const __nv_bfloat16* gl = g_Wl + widx * D * D;
    uint32_t dh = smem_u32(Wh), dl = smem_u32(Wl);
    #pragma unroll
    for (int i = tid; i < D * 16; i += 256) {
        int r = i >> 4, c = (i & 15) * 8;
        uint32_t o = (uint32_t)(r * LDS_T + c) * 2;
        cp16(dh + o, gh + r * D + c);
        cp16(dl + o, gl + r * D + c);
    }
}
__device__ __forceinline__ void load_X_split(__nv_bfloat16* Xh, __nv_bfloat16* Xl,
                                             const float* __restrict__ Xg, int tid) {
    #pragma unroll
    for (int i = tid; i < 64 * 32; i += 256) {
        int r = i >> 5, c = (i & 31) * 4;
        float4 v = *(const float4*)(Xg + (size_t)r * D + c);
        uint32_t h0, l0, h1, l1;
        split2(make_float2(v.x, v.y), h0, l0);
        split2(make_float2(v.z, v.w), h1, l1);
        *(uint32_t*)(Xh + r * LDS_T + c)     = h0;
        *(uint32_t*)(Xh + r * LDS_T + c + 2) = h1;
        *(uint32_t*)(Xl + r * LDS_T + c)     = l0;
        *(uint32_t*)(Xl + r * LDS_T + c + 2) = l1;
    }
}

// ---------------- pipelined MMA core: 64x128 tile, 8 warps (4 rg x 2 cg) ----------------
#define KOFF ((uint32_t)(16 * LDS_T * 2))   // byte stride per 16-k step in W smem

__device__ __forceinline__ void gemm_mma64(const __nv_bfloat16* Xh, const __nv_bfloat16* Xl,
                                           const __nv_bfloat16* Wh, const __nv_bfloat16* Wl,
                                           int tid, float acc[8][4]) {
    int lane = tid & 31, w = tid >> 5;
    int rg = (w & 3) * 16, cg = (w >> 2) * 64;
    #pragma unroll
    for (int i = 0; i < 8; i++)
        #pragma unroll
        for (int j = 0; j < 4; j++) acc[i][j] = 0.0f;
    int l7 = lane & 7, lm = lane >> 3;
    int a_row = rg + l7 + ((lm & 1) << 3);
    int a_cad = (lm >> 1) << 3;
    uint32_t aH = smem_u32(Xh + a_row * LDS_T + a_cad);
    uint32_t aL = smem_u32(Xl + a_row * LDS_T + a_cad);
    int b_krow = l7 + ((lm & 1) << 3);
    uint32_t bHb[4], bLb[4];
    #pragma unroll
    for (int nr = 0; nr < 4; nr++) {
        int col = cg + nr * 16 + a_cad;
        bHb[nr] = smem_u32(Wh + b_krow * LDS_T + col);
        bLb[nr] = smem_u32(Wl + b_krow * LDS_T + col);
    }

    // double-buffered fragments: A one k-step ahead, B one nr-group ahead
    uint32_t AH[2][4], AL[2][4], BH[2][4], BL[2][4];
    ldsm4(aH, AH[0]);
    ldsm4(aL, AL[0]);
    ldsm4t(bHb[0], BH[0]);
    ldsm4t(bLb[0], BL[0]);

    #pragma unroll
    for (int k = 0; k < 8; k++) {
        int ca = k & 1;
        if (k < 7) {
            ldsm4(aH + (uint32_t)(k + 1) * 32, AH[ca ^ 1]);
            ldsm4(aL + (uint32_t)(k + 1) * 32, AL[ca ^ 1]);
        }
        #pragma unroll
        for (int nr = 0; nr < 4; nr++) {
            int cb = nr & 1;
            if (nr < 3) {
                ldsm4t(bHb[nr + 1] + (uint32_t)k * KOFF, BH[cb ^ 1]);
                ldsm4t(bLb[nr + 1] + (uint32_t)k * KOFF, BL[cb ^ 1]);
            } else if (k < 7) {
                ldsm4t(bHb[0] + (uint32_t)(k + 1) * KOFF, BH[cb ^ 1]);
                ldsm4t(bLb[0] + (uint32_t)(k + 1) * KOFF, BL[cb ^ 1]);
            }
            mma16816(acc[2 * nr],     AH[ca], BH[cb][0], BH[cb][1]);
            mma16816(acc[2 * nr],     AH[ca], BL[cb][0], BL[cb][1]);
            mma16816(acc[2 * nr],     AL[ca], BH[cb][0], BH[cb][1]);
            mma16816(acc[2 * nr + 1], AH[ca], BH[cb][2], BH[cb][3]);
            mma16816(acc[2 * nr + 1], AH[ca], BL[cb][2], BL[cb][3]);
            mma16816(acc[2 * nr + 1], AL[ca], BH[cb][2], BH[cb][3]);
        }
    }
}

__device__ __forceinline__ void stage_acc(float* Cs, const float acc[8][4], int tid) {
    int lane = tid & 31, w = tid >> 5;
    int rg = (w & 3) * 16, cg = (w >> 2) * 64;
    int gid = lane >> 2, tid4 = lane & 3;
    #pragma unroll
    for (int nt = 0; nt < 8; nt++) {
        int col = cg + nt * 8 + tid4 * 2;
        int row = rg + gid;
        *(float2*)(Cs + row * LDC + col)       = make_float2(acc[nt][0], acc[nt][1]);
        *(float2*)(Cs + (row + 8) * LDC + col) = make_float2(acc[nt][2], acc[nt][3]);
    }
}
__device__ __forceinline__ void silu_ln(float v[4], const float gg[4], const float bb[4],
                                        float out[4]) {
    #pragma unroll
    for (int c = 0; c < 4; c++) v[c] = silu_f(v[c]);
    float s1 = v[0] + v[1] + v[2] + v[3];
    float s2 = v[0]*v[0] + v[1]*v[1] + v[2]*v[2] + v[3]*v[3];
    #pragma unroll
    for (int o = 16; o > 0; o >>= 1) {
        s1 += __shfl_xor_sync(0xFFFFFFFFu, s1, o);
        s2 += __shfl_xor_sync(0xFFFFFFFFu, s2, o);
    }
    float m   = s1 * (1.0f / D);
    float var = fmaxf(s2 * (1.0f / D) - m * m, 0.0f);
    float rs  = rsqrtf(var + 1e-5f);
    #pragma unroll
    for (int c = 0; c < 4; c++) out[c] = (v[c] - m) * rs * gg[c] + bb[c];
}

#define SM_SINGLE ((2 * 64 * LDS_T + 2 * D * LDS_T) * 2)
#define SM_DUAL   ((2 * 64 * LDS_T + 4 * D * LDS_T) * 2)

// ---------------- kernel 1: src @ W_s2e -> g_Ps ----------------
__global__ __launch_bounds__(256, 2) void proj_src_kernel(const float* __restrict__ src) {
    extern __shared__ char sm[];
    __nv_bfloat16* Xh = (__nv_bfloat16*)sm;
    __nv_bfloat16* Xl = Xh + 64 * LDS_T;
    __nv_bfloat16* Wh = Xl + 64 * LDS_T;
    __nv_bfloat16* Wl = Wh + D * LDS_T;
    float* Cs = (float*)sm;
    int tid = threadIdx.x;
    int row0 = blockIdx.x * 64;
    load_W_cp(Wh, Wl, 0, tid);
    cp_commit();
    load_X_split(Xh, Xl, src + (size_t)row0 * D, tid);
    cp_wait0();
    __syncthreads();
    float acc[8][4];
    gemm_mma64(Xh, Xl, Wh, Wl, tid, acc);
    __syncthreads();
    stage_acc(Cs, acc, tid);
    __syncthreads();
    int tx = tid & 31, ty = tid >> 5;
    #pragma unroll
    for (int r = 0; r < 8; r++) {
        float4 v = *(float4*)(Cs + (ty * 8 + r) * LDC + tx * 4);
        *(float4*)(g_Ps + (size_t)(row0 + ty * 8 + r) * D + tx * 4) = v;
    }
}

// ---------------- kernel 2: tgt @ W_t2e -> g_Pt ; tgt @ W_t2t -> g_Ptt ----------------
__global__ __launch_bounds__(256) void proj_tgt_dual_kernel(const float* __restrict__ tgt) {
    extern __shared__ char sm[];
    __nv_bfloat16* Xh  = (__nv_bfloat16*)sm;
    __nv_bfloat16* Xl  = Xh + 64 * LDS_T;
    __nv_bfloat16* Wh1 = Xl + 64 * LDS_T;
    __nv_bfloat16* Wl1 = Wh1 + D * LDS_T;
    __nv_bfloat16* Wh2 = Wl1 + D * LDS_T;
    __nv_bfloat16* Wl2 = Wh2 + D * LDS_T;
    float* Cs = (float*)Wh1;
    int tid = threadIdx.x;
    int row0 = blockIdx.x * 64;
    load_W_cp(Wh1, Wl1, 1, tid);
    load_W_cp(Wh2, Wl2, 4, tid);
    cp_commit();
    load_X_split(Xh, Xl, tgt + (size_t)row0 * D, tid);
    cp_wait0();
    __syncthreads();
    int tx = tid & 31, ty = tid >> 5;
    {
        float acc[8][4];
        gemm_mma64(Xh, Xl, Wh1, Wl1, tid, acc);
        __syncthreads();
        stage_acc(Cs, acc, tid);
        __syncthreads();
        #pragma unroll
        for (int r = 0; r < 8; r++) {
            float4 v = *(float4*)(Cs + (ty * 8 + r) * LDC + tx * 4);
            *(float4*)(g_Pt + (size_t)(row0 + ty * 8 + r) * D + tx * 4) = v;
        }
        __syncthreads();
    }
    {
        float acc[8][4];
        gemm_mma64(Xh, Xl, Wh2, Wl2, tid, acc);
        __syncthreads();
        stage_acc(Cs, acc, tid);
        __syncthreads();
        #pragma unroll
        for (int r = 0; r < 8; r++) {
            float4 v = *(float4*)(Cs + (ty * 8 + r) * LDC + tx * 4);
            *(float4*)(g_Ptt + (size_t)(row0 + ty * 8 + r) * D + tx * 4) = v;
        }
    }
}

// ---------------- kernel 3: d_bond = LN(silu(bond@W_e2e + gather(Ps) + gather(Pt))) ----------------
__global__ __launch_bounds__(256, 2) void bond_kernel(const float* __restrict__ bond,
                                                      const float* __restrict__ g1,
                                                      const float* __restrict__ b1,
                                                      const int* __restrict__ src_order,
                                                      const int* __restrict__ tgt_order,
                                                      float* __restrict__ out0) {
    extern __shared__ char sm[];
    __nv_bfloat16* Xh = (__nv_bfloat16*)sm;
    __nv_bfloat16* Xl = Xh + 64 * LDS_T;
    __nv_bfloat16* Wh = Xl + 64 * LDS_T;
    __nv_bfloat16* Wl = Wh + D * LDS_T;
    float* Cs = (float*)sm;
    int tid = threadIdx.x;
    int tx = tid & 31, ty = tid >> 5;
    int row0 = blockIdx.x * 64;           // global row in [0, B*E)
    int b    = row0 / En;                 // tile never crosses batch (E % 64 == 0)
    int ebase = row0 - b * En;

    load_W_cp(Wh, Wl, 2, tid);            // W_e2e (async)
    cp_commit();
    load_X_split(Xh, Xl, bond + (size_t)row0 * D, tid);

    // pre-MMA: load gather indices + prefetch Ps/Pt sectors into L2
    {
        int rr = tx >> 2, sec = tx & 3;   // 8 rows x 4 sectors per warp
        int e = ebase + ty * 8 + rr;
        int so_ = src_order[e];
        int to_ = tgt_order[e];
        pref_l2(g_Ps + ((size_t)b * NSn + so_) * D + sec * 32);
        pref_l2(g_Pt + ((size_t)b * NTn + to_) * D + sec * 32);
    }

    cp_wait0();
    __syncthreads();
    float acc[8][4];
    gemm_mma64(Xh, Xl, Wh, Wl, tid, acc);
    __syncthreads();
    stage_acc(Cs, acc, tid);
    __syncthreads();

    float gg[4], bb[4];
    #pragma unroll
    for (int c = 0; c < 4; c++) { gg[c] = g1[tx * 4 + c]; bb[c] = b1[tx * 4 + c]; }

    #pragma unroll
    for (int r = 0; r < 8; r++) {
        int row = row0 + ty * 8 + r;
        int e   = ebase + ty * 8 + r;
        int so  = src_order[e];
        int to  = tgt_order[e];
        float4 cv = *(float4*)(Cs + (ty * 8 + r) * LDC + tx * 4);
        float4 ps = *(const float4*)(g_Ps + ((size_t)b * NSn + so) * D + tx * 4);
        float4 pt = *(const float4*)(g_Pt + ((size_t)b * NTn + to) * D + tx * 4);
        float v[4];
        v[0] = cv.x + ps.x + pt.x;
        v[1] = cv.y + ps.y + pt.y;
        v[2] = cv.z + ps.z + pt.z;
        v[3] = cv.w + ps.w + pt.w;
        float d[4];
        silu_ln(v, gg, bb, d);
        float4 xin = *(const float4*)(bond + (size_t)row * D + tx * 4);
        float4 db = {d[0], d[1], d[2], d[3]};
        float4 o0 = {xin.x + d[0], xin.y + d[1], xin.z + d[2], xin.w + d[3]};
        *(float4*)(g_db + (size_t)row * D + tx * 4) = db;
        *(float4*)(out0 + (size_t)row * D + tx * 4) = o0;
    }
}

// ---------------- kernel 4: bond_reduce = mean_k(coef * d_bond[edge_order]) ----------------
__global__ __launch_bounds__(256) void reduce_kernel(const int* __restrict__ edge_order,
                                                     const float* __restrict__ coef) {
    int tid  = threadIdx.x;
    int lane = tid & 31;
    int node = (blockIdx.x * blockDim.x + tid) >> 5;
    int b = node / NTn;
    int t = node - b * NTn;
    int   e_l = 0;
    float c_l = 0.0f;
    if (lane < Kc) {
        e_l = edge_order[t * Kc + lane];
        c_l = coef[t * Kc + lane];
    }
    float4 acc = {0.f, 0.f, 0.f, 0.f};
    #pragma unroll
    for (int k = 0; k < Kc; k++) {
        int   e = __shfl_sync(0xFFFFFFFFu, e_l, k);
        float c = __shfl_sync(0xFFFFFFFFu, c_l, k);
        float4 v = *(const float4*)(g_db + ((size_t)b * En + e) * D + lane * 4);
        acc.x += c * v.x;
        acc.y += c * v.y;
        acc.z += c * v.z;
        acc.w += c * v.w;
    }
    const float inv = 1.0f / Kc;
    acc.x *= inv; acc.y *= inv; acc.z *= inv; acc.w *= inv;
    *(float4*)(g_red + (size_t)node * D + lane * 4) = acc;
}

// ---------------- kernel 5: d_tgt = LN(silu(red@W_e2t + Ptt)) ; out = tgt + d_tgt ----------------
__global__ __launch_bounds__(256, 2) void tgt_kernel(const float* __restrict__ tgt,
                                                     const float* __restrict__ g2,
                                                     const float* __restrict__ b2,
                                                     float* __restrict__ out2) {
    extern __shared__ char sm[];
    __nv_bfloat16* Xh = (__nv_bfloat16*)sm;
    __nv_bfloat16* Xl = Xh + 64 * LDS_T;
    __nv_bfloat16* Wh = Xl + 64 * LDS_T;
    __nv_bfloat16* Wl = Wh + D * LDS_T;
    float* Cs = (float*)sm;
    int tid = threadIdx.x;
    int row0 = blockIdx.x * 64;
    load_W_cp(Wh, Wl, 3, tid);
    cp_commit();
    load_X_split(Xh, Xl, g_red + (size_t)row0 * D, tid);
    cp_wait0();
    __syncthreads();
    float acc[8][4];
    gemm_mma64(Xh, Xl, Wh, Wl, tid, acc);
    __syncthreads();
    stage_acc(Cs, acc, tid);
    __syncthreads();

    int tx = tid & 31, ty = tid >> 5;
    float gg[4], bb[4];
    #pragma unroll
    for (int c = 0; c < 4; c++) { gg[c] = g2[tx * 4 + c]; bb[c] = b2[tx * 4 + c]; }
    #pragma unroll
    for (int r = 0; r < 8; r++) {
        int row = row0 + ty * 8 + r;
        float4 cv = *(float4*)(Cs + (ty * 8 + r) * LDC + tx * 4);
        float4 pt = *(const float4*)(g_Ptt + (size_t)row * D + tx * 4);
        float v[4];
        v[0] = cv.x + pt.x;
        v[1] = cv.y + pt.y;
        v[2] = cv.z + pt.z;
        v[3] = cv.w + pt.w;
        float d[4];
        silu_ln(v, gg, bb, d);
        float4 tin = *(const float4*)(tgt + (size_t)row * D + tx * 4);
        float4 o2 = {tin.x + d[0], tin.y + d[1], tin.z + d[2], tin.w + d[3]};
        *(float4*)(out2 + (size_t)row * D + tx * 4) = o2;
    }
}

// ---------------- launch ----------------
extern "C" void kernel_launch(void* const* d_in, const int* in_sizes, int n_in,
                              void* d_out, int out_size) {
    const float* bond  = (const float*)d_in[0];
    const float* src   = (const float*)d_in[1];
    const float* tgt   = (const float*)d_in[2];
    const float* W_s2e = (const float*)d_in[3];
    const float* W_t2e = (const float*)d_in[4];
    const float* W_e2e = (const float*)d_in[5];
    const float* ln1_g = (const float*)d_in[6];
    const float* ln1_b = (const float*)d_in[7];
    const float* W_e2t = (const float*)d_in[8];
    const float* W_t2t = (const float*)d_in[9];
    const float* ln2_g = (const float*)d_in[10];
    const float* ln2_b = (const float*)d_in[11];
    const float* coef  = (const float*)d_in[12];
    const int*   so    = (const int*)d_in[13];
    const int*   to    = (const int*)d_in[14];
    const int*   eo    = (const int*)d_in[15];

    float* out  = (float*)d_out;
    float* out0 = out;                                   // bond + d_bond   [B,E,D]
    float* out1 = out0 + (size_t)Bn * En * D;            // src passthrough [B,NS,D]
    float* out2 = out1 + (size_t)Bn * NSn * D;           // tgt + d_tgt     [B,NT,D]

    cudaFuncSetAttribute(proj_src_kernel,      cudaFuncAttributeMaxDynamicSharedMemorySize, SM_SINGLE);
    cudaFuncSetAttribute(proj_tgt_dual_kernel, cudaFuncAttributeMaxDynamicSharedMemorySize, SM_DUAL);
    cudaFuncSetAttribute(bond_kernel,          cudaFuncAttributeMaxDynamicSharedMemorySize, SM_SINGLE);
    cudaFuncSetAttribute(tgt_kernel,           cudaFuncAttributeMaxDynamicSharedMemorySize, SM_SINGLE);

    prep_w_kernel<<<320, 256>>>(W_s2e, W_t2e, W_e2e, W_e2t, W_t2t);

    proj_src_kernel<<<(Bn * NSn) / 64, 256, SM_SINGLE>>>(src);
    proj_tgt_dual_kernel<<<(Bn * NTn) / 64, 256, SM_DUAL>>>(tgt);

    cudaMemcpyAsync(out1, src, (size_t)Bn * NSn * D * sizeof(float),
                    cudaMemcpyDeviceToDevice, 0);

    bond_kernel<<<(Bn * En) / 64, 256, SM_SINGLE>>>(bond, ln1_g, ln1_b, so, to, out0);

    reduce_kernel<<<(Bn * NTn) / 8, 256>>>(eo, coef);

    tgt_kernel<<<(Bn * NTn) / 64, 256, SM_SINGLE>>>(tgt, ln2_g, ln2_b, out2);
}